// round 2
// baseline (speedup 1.0000x reference)
#include <cuda_runtime.h>
#include <cuda_fp16.h>
#include <math.h>

#define NN 50000
#define EE 1600000
#define HH 64
#define FIN 8
#define PP 5
#define LL 3
#define CI 68   // H + 4
#define SCAN_BLK 256
#define NBLK ((NN + SCAN_BLK - 1) / SCAN_BLK)   // 196

// ---------------- scratch (device globals; no allocation) ----------------
__device__ float g_deg[NN];
__device__ float g_dis[NN];
__device__ int   g_cnt[NN];
__device__ int   g_fill[NN];
__device__ int   g_rowptr[NN + 1];
__device__ int   g_part[SCAN_BLK];        // block partial sums (padded)
__device__ int   g_cols[EE];
__device__ float g_wv[EE];
__device__ float g_h[NN * HH];            // fp32 master h
__device__ __half g_hh[NN * HH];          // fp16 mirror of h (gather operand)
__device__ __half g_t0h[NN * HH];         // fp16 tx ping
__device__ __half g_t1h[NN * HH];         // fp16 tx pong
__device__ float g_res[NN * HH];
__device__ __half g_Ah[NN * HH];          // edge-pred A (fp16)
__device__ __half g_Bh[NN * HH];          // edge-pred B (fp16)
__device__ float g_colsum[HH];
__device__ float g_sumsq;
__device__ float g_coeffs[PP + 1];

// packed dual-fp32 FMA (sm_103a): d = a*b + c elementwise on 2 floats
__device__ __forceinline__ unsigned long long ffma2(unsigned long long a,
                                                    unsigned long long b,
                                                    unsigned long long c) {
    unsigned long long d;
    asm("fma.rn.f32x2 %0, %1, %2, %3;" : "=l"(d) : "l"(a), "l"(b), "l"(c));
    return d;
}

// ---------------- graph build ----------------
__global__ void zero_build_kernel() {
    int i = blockIdx.x * blockDim.x + threadIdx.x;
    if (i < NN) { g_deg[i] = 0.f; g_cnt[i] = 0; g_fill[i] = 0; }
}

__global__ void deghist_kernel(const int* __restrict__ ei, const float* __restrict__ ew) {
    int e = blockIdx.x * blockDim.x + threadIdx.x;
    if (e >= EE) return;
    atomicAdd(&g_deg[ei[EE + e]], ew[e]);   // deg at col
    atomicAdd(&g_cnt[ei[e]], 1);            // count at row
}

__global__ void dis_kernel() {
    int n = blockIdx.x * blockDim.x + threadIdx.x;
    if (n >= NN) return;
    float d = g_deg[n];
    float v = rsqrtf(d);           // d==0 -> inf
    v = fminf(v, 1e6f);            // clamp like reference
    g_dis[n] = v;
}

// 3-phase parallel scan over g_cnt -> g_rowptr
__global__ void scan_partial_kernel() {
    __shared__ int red[SCAN_BLK];
    int tid = threadIdx.x;
    int i = blockIdx.x * SCAN_BLK + tid;
    int v = (i < NN) ? g_cnt[i] : 0;
    red[tid] = v;
    __syncthreads();
    for (int o = SCAN_BLK / 2; o > 0; o >>= 1) {
        if (tid < o) red[tid] += red[tid + o];
        __syncthreads();
    }
    if (tid == 0) g_part[blockIdx.x] = red[0];
}

__global__ void scan_spine_kernel() {
    __shared__ int s[SCAN_BLK];
    int tid = threadIdx.x;
    int v = (tid < NBLK) ? g_part[tid] : 0;
    s[tid] = v;
    __syncthreads();
    for (int o = 1; o < SCAN_BLK; o <<= 1) {
        int t = (tid >= o) ? s[tid - o] : 0;
        __syncthreads();
        s[tid] += t;
        __syncthreads();
    }
    g_part[tid] = (tid == 0) ? 0 : s[tid - 1];   // exclusive
    if (tid == SCAN_BLK - 1) g_rowptr[NN] = s[tid];
}

__global__ void scan_write_kernel() {
    __shared__ int s[SCAN_BLK];
    int tid = threadIdx.x;
    int i = blockIdx.x * SCAN_BLK + tid;
    int v = (i < NN) ? g_cnt[i] : 0;
    s[tid] = v;
    __syncthreads();
    for (int o = 1; o < SCAN_BLK; o <<= 1) {
        int t = (tid >= o) ? s[tid - o] : 0;
        __syncthreads();
        s[tid] += t;
        __syncthreads();
    }
    if (i < NN) g_rowptr[i] = g_part[blockIdx.x] + s[tid] - v;   // exclusive
}

__global__ void scatter_kernel(const int* __restrict__ ei, const float* __restrict__ ew) {
    int e = blockIdx.x * blockDim.x + threadIdx.x;
    if (e >= EE) return;
    int r = ei[e], c = ei[EE + e];
    int pos = g_rowptr[r] + atomicAdd(&g_fill[r], 1);
    g_cols[pos] = c;
    g_wv[pos]   = g_dis[r] * ew[e] * g_dis[c];
}

// ---------------- input projection ----------------
__global__ void inproj_kernel(const float* __restrict__ x,
                              const float* __restrict__ W,
                              const float* __restrict__ b) {
    int g = blockIdx.x * blockDim.x + threadIdx.x;
    if (g >= NN * HH) return;
    int n = g >> 6, f = g & 63;
    float s = b[f];
#pragma unroll
    for (int i = 0; i < FIN; ++i) s += x[n * FIN + i] * W[f * FIN + i];
    g_h[g] = s;
    g_hh[g] = __float2half(s);
}

// ---------------- per-layer stats + coeff MLP ----------------
__global__ void zero_stats_kernel() {
    int t = threadIdx.x;
    if (t < HH) g_colsum[t] = 0.f;
    if (t == HH) g_sumsq = 0.f;
}

__global__ void stats_kernel() {
    __shared__ float red[256];
    int tid = threadIdx.x;
    int colf = tid & 63;
    float ls = 0.f, lss = 0.f;
    for (int n = blockIdx.x * 4 + (tid >> 6); n < NN; n += gridDim.x * 4) {
        float v = g_h[n * HH + colf];
        ls += v; lss += v * v;
    }
    red[tid] = ls;
    __syncthreads();
    if (tid < 64) {
        float c = red[tid] + red[tid + 64] + red[tid + 128] + red[tid + 192];
        atomicAdd(&g_colsum[tid], c);
    }
    __syncthreads();
    red[tid] = lss;
    __syncthreads();
    for (int o = 128; o > 0; o >>= 1) {
        if (tid < o) red[tid] += red[tid + o];
        __syncthreads();
    }
    if (tid == 0) atomicAdd(&g_sumsq, red[0]);
}

__global__ void coeff_kernel(const float* __restrict__ cW1, const float* __restrict__ cb1,
                             const float* __restrict__ cW2, const float* __restrict__ cb2) {
    __shared__ float ci[CI];
    __shared__ float hid[32];
    __shared__ float logit[PP + 1];
    int t = threadIdx.x;
    if (t < HH) ci[t] = g_colsum[t] / (float)NN;
    __syncthreads();
    if (t == 0) {
        float tot = 0.f;
        for (int i = 0; i < HH; ++i) tot += g_colsum[i];
        const float M = (float)NN * (float)HH;
        float mean = tot / M;
        float var  = (g_sumsq - tot * tot / M) / (M - 1.0f);   // unbiased
        ci[64] = mean;
        ci[65] = sqrtf(fmaxf(var, 0.f));
        ci[66] = (float)NN;
        ci[67] = (float)EE;
    }
    __syncthreads();
    if (t < 32) {
        float s = cb1[t];
        for (int i = 0; i < CI; ++i) s += cW1[t * CI + i] * ci[i];
        hid[t] = fmaxf(s, 0.f);
    }
    __syncthreads();
    if (t < PP + 1) {
        float s = cb2[t];
        for (int i = 0; i < 32; ++i) s += cW2[t * 32 + i] * hid[i];
        logit[t] = s;
    }
    __syncthreads();
    if (t == 0) {
        float mx = logit[0];
        for (int i = 1; i <= PP; ++i) mx = fmaxf(mx, logit[i]);
        float den = 0.f, ex[PP + 1];
        for (int i = 0; i <= PP; ++i) { ex[i] = expf(logit[i] - mx); den += ex[i]; }
        for (int i = 0; i <= PP; ++i) g_coeffs[i] = ex[i] / den;
    }
}

// ---------------- SpMM (gather-CSR fp16 operand, warp per row, no atomics) ----------------
__global__ void spmm_kernel(int k) {
    int gw = (blockIdx.x * blockDim.x + threadIdx.x) >> 5;
    if (gw >= NN) return;
    int lane = threadIdx.x & 31;

    const __half2* tin = (k == 1) ? (const __half2*)g_hh
                       : (k & 1)  ? (const __half2*)g_t1h
                                  : (const __half2*)g_t0h;
    __half2* tout = (k & 1) ? (__half2*)g_t0h : (__half2*)g_t1h;

    int s = g_rowptr[gw], e = g_rowptr[gw + 1];
    float ax = 0.f, ay = 0.f;
#pragma unroll 4
    for (int j = s; j < e; ++j) {
        int cc  = __ldg(&g_cols[j]);             // broadcast
        float w = __ldg(&g_wv[j]);
        float2 v = __half22float2(__ldg(&tin[cc * 32 + lane]));  // 128B/warp
        ax += w * v.x; ay += w * v.y;
    }
    int o = gw * 32 + lane;
    tout[o] = __floats2half2_rn(ax, ay);

    float ck = g_coeffs[k];
    float2 r;
    if (k == 1) {
        float2 hv = ((const float2*)g_h)[o];
        float c0 = g_coeffs[0];
        r.x = c0 * hv.x + ck * ax;
        r.y = c0 * hv.y + ck * ay;
    } else {
        r = ((float2*)g_res)[o];
        r.x += ck * ax;
        r.y += ck * ay;
    }
    ((float2*)g_res)[o] = r;
}

// ---------------- residual + LayerNorm (warp per node) ----------------
__global__ void ln_kernel(const float* __restrict__ scale, const float* __restrict__ bias,
                          float* outh) {
    int gw = (blockIdx.x * blockDim.x + threadIdx.x) >> 5;
    if (gw >= NN) return;
    int lane = threadIdx.x & 31;
    int o = gw * 32 + lane;
    float2 hv = ((const float2*)g_h)[o];
    float2 rv = ((const float2*)g_res)[o];
    float vx = hv.x + rv.x, vy = hv.y + rv.y;
    float s = vx + vy;
#pragma unroll
    for (int d = 16; d; d >>= 1) s += __shfl_xor_sync(0xffffffffu, s, d);
    float m = s * (1.0f / HH);
    float dx = vx - m, dy = vy - m;
    float q = dx * dx + dy * dy;
#pragma unroll
    for (int d = 16; d; d >>= 1) q += __shfl_xor_sync(0xffffffffu, q, d);
    float inv = rsqrtf(q * (1.0f / HH) + 1e-5f);
    float ox = dx * inv * scale[2 * lane]     + bias[2 * lane];
    float oy = dy * inv * scale[2 * lane + 1] + bias[2 * lane + 1];
    ((float2*)g_h)[o] = make_float2(ox, oy);
    ((__half2*)g_hh)[o] = __floats2half2_rn(ox, oy);
    if (outh) ((float2*)outh)[o] = make_float2(ox, oy);
}

// ---------------- edge predictor: A = h@W1a^T, B = h@W1b^T (stored fp16) ----------------
__global__ void abgemm_kernel(const float* __restrict__ epW1) {
    __shared__ float WtA[64 * 64];
    __shared__ float WtB[64 * 64];
    __shared__ float hs[4 * 64];
    int tid = threadIdx.x;
    for (int idx = tid; idx < 4096; idx += 256) {
        int f = idx >> 6, i = idx & 63;
        WtA[i * 64 + f] = epW1[f * 128 + i];        // W1[:, :64]
        WtB[i * 64 + f] = epW1[f * 128 + 64 + i];   // W1[:, 64:]
    }
    int n0 = blockIdx.x * 4;
    hs[tid] = g_h[n0 * 64 + tid];
    __syncthreads();
    int ln = tid >> 6, f = tid & 63;
    float a = 0.f, b = 0.f;
#pragma unroll
    for (int i = 0; i < 64; ++i) {
        float hv = hs[ln * 64 + i];
        a += hv * WtA[i * 64 + f];
        b += hv * WtB[i * 64 + f];
    }
    g_Ah[(n0 + ln) * 64 + f] = __float2half(a);
    g_Bh[(n0 + ln) * 64 + f] = __float2half(b);
}

__global__ void __launch_bounds__(128)
edge_kernel(const int* __restrict__ ei,
            const float* __restrict__ epb1,
            const float* __restrict__ epW2, const float* __restrict__ epb2,
            const float* __restrict__ epW3, const float* __restrict__ epb3,
            float* __restrict__ out) {
    __shared__ float W2s[32 * 64];
    __shared__ float b1s[64];
    __shared__ float b2s[32];
    __shared__ float W3s[32];
    __shared__ float b3s;
    int tid = threadIdx.x;
    for (int idx = tid; idx < 2048; idx += 128) W2s[idx] = epW2[idx];
    if (tid < 64) b1s[tid] = epb1[tid];
    if (tid < 32) { b2s[tid] = epb2[tid]; W3s[tid] = epW3[tid]; }
    if (tid == 0) b3s = epb3[0];
    __syncthreads();

    int e = blockIdx.x * 128 + tid;
    if (e >= EE) return;
    int r = ei[e], c = ei[EE + e];
    const __half2* Ar = (const __half2*)(g_Ah + r * 64);
    const __half2* Bc = (const __half2*)(g_Bh + c * 64);
    const float2* b1v = (const float2*)b1s;
    float2 e1[32];
#pragma unroll
    for (int i = 0; i < 32; ++i) {
        float2 av = __half22float2(__ldg(&Ar[i]));
        float2 bv = __half22float2(__ldg(&Bc[i]));
        float2 bb = b1v[i];
        e1[i].x = fmaxf(av.x + bv.x + bb.x, 0.f);
        e1[i].y = fmaxf(av.y + bv.y + bb.y, 0.f);
    }
    const unsigned long long* e1p = (const unsigned long long*)e1;
    float acc = b3s;
#pragma unroll
    for (int o = 0; o < 32; ++o) {
        const unsigned long long* wv = (const unsigned long long*)(W2s + o * 64);
        float2 init = make_float2(b2s[o], 0.f);
        unsigned long long a2 = *(const unsigned long long*)&init;
#pragma unroll
        for (int i = 0; i < 32; ++i) a2 = ffma2(wv[i], e1p[i], a2);
        float2 sv = *(const float2*)&a2;
        acc += W3s[o] * fmaxf(sv.x + sv.y, 0.f);
    }
    out[e] = 1.0f / (1.0f + expf(-acc));
}

// ---------------- launch ----------------
extern "C" void kernel_launch(void* const* d_in, const int* in_sizes, int n_in,
                              void* d_out, int out_size) {
    const float* x    = (const float*)d_in[0];
    const int*   ei   = (const int*)d_in[1];
    const float* ew   = (const float*)d_in[2];
    const float* W_in = (const float*)d_in[3];
    const float* b_in = (const float*)d_in[4];
    const float* cW1  = (const float*)d_in[5];
    const float* cb1  = (const float*)d_in[6];
    const float* cW2  = (const float*)d_in[7];
    const float* cb2  = (const float*)d_in[8];
    const float* lns  = (const float*)d_in[9];
    const float* lnb  = (const float*)d_in[10];
    const float* epW1 = (const float*)d_in[11];
    const float* epb1 = (const float*)d_in[12];
    const float* epW2 = (const float*)d_in[13];
    const float* epb2 = (const float*)d_in[14];
    const float* epW3 = (const float*)d_in[15];
    const float* epb3 = (const float*)d_in[16];
    float* out = (float*)d_out;

    const int NB = (NN + 255) / 256;
    const int EB = (EE + 255) / 256;
    const int WB = (NN * 32 + 255) / 256;   // warp-per-node grids (6250)

    // graph build (CSR + symmetric normalization)
    zero_build_kernel<<<NB, 256>>>();
    deghist_kernel<<<EB, 256>>>(ei, ew);
    dis_kernel<<<NB, 256>>>();
    scan_partial_kernel<<<NBLK, SCAN_BLK>>>();
    scan_spine_kernel<<<1, SCAN_BLK>>>();
    scan_write_kernel<<<NBLK, SCAN_BLK>>>();
    scatter_kernel<<<EB, 256>>>(ei, ew);

    // input projection
    inproj_kernel<<<(NN * HH + 255) / 256, 256>>>(x, W_in, b_in);

    // diffusion layers
    for (int l = 0; l < LL; ++l) {
        zero_stats_kernel<<<1, 128>>>();
        stats_kernel<<<1024, 256>>>();
        coeff_kernel<<<1, 128>>>(cW1 + l * 32 * CI, cb1 + l * 32,
                                 cW2 + l * (PP + 1) * 32, cb2 + l * (PP + 1));
        for (int k = 1; k <= PP; ++k)
            spmm_kernel<<<WB, 256>>>(k);
        ln_kernel<<<WB, 256>>>(lns + l * HH, lnb + l * HH,
                               (l == LL - 1) ? (out + EE) : (float*)nullptr);
    }

    // edge predictor
    abgemm_kernel<<<NN / 4, 256>>>(epW1);
    edge_kernel<<<(EE + 127) / 128, 128>>>(ei, epb1, epW2, epb2, epW3, epb3, out);
}

// round 3
// speedup vs baseline: 1.2742x; 1.2742x over previous
#include <cuda_runtime.h>
#include <cuda_fp16.h>
#include <math.h>

#define NN 50000
#define EE 1600000
#define HH 64
#define FIN 8
#define PP 5
#define LL 3
#define CI 68   // H + 4
#define SCAN_BLK 256
#define NBLK ((NN + SCAN_BLK - 1) / SCAN_BLK)   // 196

// ---------------- scratch (device globals; no allocation) ----------------
__device__ float g_deg[NN];
__device__ float g_dis[NN];
__device__ int   g_cnt[NN];
__device__ int   g_fill[NN];
__device__ int   g_rowptr[NN + 1];
__device__ int   g_part[SCAN_BLK];
__device__ int2  g_cw[EE + 4];            // packed (col, w-bits)
__device__ float g_h[NN * HH];            // fp32 master h
__device__ __half g_hh[NN * HH];          // fp16 mirror of h
__device__ __half g_t0h[NN * HH];         // fp16 tx ping
__device__ __half g_t1h[NN * HH];         // fp16 tx pong
__device__ float g_res[NN * HH];
__device__ __half g_Ah[NN * HH];          // edge-pred A (fp16)
__device__ __half g_Bh[NN * HH];          // edge-pred B (fp16)
__device__ float g_colsum[HH];
__device__ float g_sumsq;
__device__ float g_coeffs[PP + 1];

// packed dual-fp32 FMA (sm_103a)
__device__ __forceinline__ unsigned long long ffma2(unsigned long long a,
                                                    unsigned long long b,
                                                    unsigned long long c) {
    unsigned long long d;
    asm("fma.rn.f32x2 %0, %1, %2, %3;" : "=l"(d) : "l"(a), "l"(b), "l"(c));
    return d;
}
__device__ __forceinline__ unsigned long long pack2(float x, float y) {
    float2 t = make_float2(x, y);
    return *(unsigned long long*)&t;
}

// ---------------- graph build ----------------
__global__ void zero_build_kernel() {
    int i = blockIdx.x * blockDim.x + threadIdx.x;
    if (i < NN) { g_deg[i] = 0.f; g_cnt[i] = 0; g_fill[i] = 0; }
}

__global__ void deghist_kernel(const int* __restrict__ ei, const float* __restrict__ ew) {
    int e = blockIdx.x * blockDim.x + threadIdx.x;
    if (e >= EE) return;
    atomicAdd(&g_deg[ei[EE + e]], ew[e]);
    atomicAdd(&g_cnt[ei[e]], 1);
}

__global__ void dis_kernel() {
    int n = blockIdx.x * blockDim.x + threadIdx.x;
    if (n >= NN) return;
    float v = rsqrtf(g_deg[n]);
    g_dis[n] = fminf(v, 1e6f);
}

__global__ void scan_partial_kernel() {
    __shared__ int red[SCAN_BLK];
    int tid = threadIdx.x;
    int i = blockIdx.x * SCAN_BLK + tid;
    red[tid] = (i < NN) ? g_cnt[i] : 0;
    __syncthreads();
    for (int o = SCAN_BLK / 2; o > 0; o >>= 1) {
        if (tid < o) red[tid] += red[tid + o];
        __syncthreads();
    }
    if (tid == 0) g_part[blockIdx.x] = red[0];
}

__global__ void scan_spine_kernel() {
    __shared__ int s[SCAN_BLK];
    int tid = threadIdx.x;
    s[tid] = (tid < NBLK) ? g_part[tid] : 0;
    __syncthreads();
    for (int o = 1; o < SCAN_BLK; o <<= 1) {
        int t = (tid >= o) ? s[tid - o] : 0;
        __syncthreads();
        s[tid] += t;
        __syncthreads();
    }
    g_part[tid] = (tid == 0) ? 0 : s[tid - 1];
    if (tid == SCAN_BLK - 1) g_rowptr[NN] = s[tid];
}

__global__ void scan_write_kernel() {
    __shared__ int s[SCAN_BLK];
    int tid = threadIdx.x;
    int i = blockIdx.x * SCAN_BLK + tid;
    int v = (i < NN) ? g_cnt[i] : 0;
    s[tid] = v;
    __syncthreads();
    for (int o = 1; o < SCAN_BLK; o <<= 1) {
        int t = (tid >= o) ? s[tid - o] : 0;
        __syncthreads();
        s[tid] += t;
        __syncthreads();
    }
    if (i < NN) g_rowptr[i] = g_part[blockIdx.x] + s[tid] - v;
}

__global__ void scatter_kernel(const int* __restrict__ ei, const float* __restrict__ ew) {
    int e = blockIdx.x * blockDim.x + threadIdx.x;
    if (e >= EE) return;
    int r = ei[e], c = ei[EE + e];
    int pos = g_rowptr[r] + atomicAdd(&g_fill[r], 1);
    float w = g_dis[r] * ew[e] * g_dis[c];
    g_cw[pos] = make_int2(c, __float_as_int(w));
}

// ---------------- input projection ----------------
__global__ void inproj_kernel(const float* __restrict__ x,
                              const float* __restrict__ W,
                              const float* __restrict__ b) {
    int g = blockIdx.x * blockDim.x + threadIdx.x;
    if (g >= NN * HH) return;
    int n = g >> 6, f = g & 63;
    float s = b[f];
#pragma unroll
    for (int i = 0; i < FIN; ++i) s += x[n * FIN + i] * W[f * FIN + i];
    g_h[g] = s;
    g_hh[g] = __float2half(s);
}

// ---------------- per-layer stats + coeff MLP ----------------
__global__ void zero_stats_kernel() {
    int t = threadIdx.x;
    if (t < HH) g_colsum[t] = 0.f;
    if (t == HH) g_sumsq = 0.f;
}

__global__ void stats_kernel() {
    __shared__ float red[256];
    int tid = threadIdx.x;
    int colf = tid & 63;
    float ls = 0.f, lss = 0.f;
    for (int n = blockIdx.x * 4 + (tid >> 6); n < NN; n += gridDim.x * 4) {
        float v = g_h[n * HH + colf];
        ls += v; lss += v * v;
    }
    red[tid] = ls;
    __syncthreads();
    if (tid < 64) {
        float c = red[tid] + red[tid + 64] + red[tid + 128] + red[tid + 192];
        atomicAdd(&g_colsum[tid], c);
    }
    __syncthreads();
    red[tid] = lss;
    __syncthreads();
    for (int o = 128; o > 0; o >>= 1) {
        if (tid < o) red[tid] += red[tid + o];
        __syncthreads();
    }
    if (tid == 0) atomicAdd(&g_sumsq, red[0]);
}

__global__ void coeff_kernel(const float* __restrict__ cW1, const float* __restrict__ cb1,
                             const float* __restrict__ cW2, const float* __restrict__ cb2) {
    __shared__ float ci[CI];
    __shared__ float hid[32];
    __shared__ float logit[PP + 1];
    int t = threadIdx.x;
    if (t < HH) ci[t] = g_colsum[t] / (float)NN;
    __syncthreads();
    if (t == 0) {
        float tot = 0.f;
        for (int i = 0; i < HH; ++i) tot += g_colsum[i];
        const float M = (float)NN * (float)HH;
        float mean = tot / M;
        float var  = (g_sumsq - tot * tot / M) / (M - 1.0f);
        ci[64] = mean;
        ci[65] = sqrtf(fmaxf(var, 0.f));
        ci[66] = (float)NN;
        ci[67] = (float)EE;
    }
    __syncthreads();
    if (t < 32) {
        float s = cb1[t];
        for (int i = 0; i < CI; ++i) s += cW1[t * CI + i] * ci[i];
        hid[t] = fmaxf(s, 0.f);
    }
    __syncthreads();
    if (t < PP + 1) {
        float s = cb2[t];
        for (int i = 0; i < 32; ++i) s += cW2[t * 32 + i] * hid[i];
        logit[t] = s;
    }
    __syncthreads();
    if (t == 0) {
        float mx = logit[0];
        for (int i = 1; i <= PP; ++i) mx = fmaxf(mx, logit[i]);
        float den = 0.f, ex[PP + 1];
        for (int i = 0; i <= PP; ++i) { ex[i] = expf(logit[i] - mx); den += ex[i]; }
        for (int i = 0; i <= PP; ++i) g_coeffs[i] = ex[i] / den;
    }
}

// ---------------- SpMM v3: warp per row, 4 neighbors per step, coalesced ----------------
// 8 lanes (fl=0..7) cover a 128B fp16 row; sub=lane>>3 picks neighbor in group of 4.
// fuse != 0: k==PP, do residual + LayerNorm inline.
__global__ void spmm_kernel(int k, int fuse,
                            const float* __restrict__ lnsc,
                            const float* __restrict__ lnbi,
                            float* outh) {
    int row = (blockIdx.x * blockDim.x + threadIdx.x) >> 5;
    if (row >= NN) return;
    int lane = threadIdx.x & 31;
    int sub = lane >> 3, fl = lane & 7;

    const __half* tin = (k == 1) ? g_hh : ((k & 1) ? g_t1h : g_t0h);
    __half* tout = (k & 1) ? g_t0h : g_t1h;

    int s = g_rowptr[row], e = g_rowptr[row + 1];
    unsigned long long a0 = 0ull, a1 = 0ull, a2 = 0ull, a3 = 0ull;

    for (int j = s; j < e; j += 4) {
        int jj = j + sub;
        int2 cw = __ldg(&g_cw[jj]);
        bool ok = (jj < e);
        int cc = ok ? cw.x : 0;
        float w = ok ? __int_as_float(cw.y) : 0.f;
        uint4 d = __ldg((const uint4*)tin + cc * 8 + fl);
        unsigned long long wp = pack2(w, w);
        const __half2* hp = (const __half2*)&d;
        float2 v0 = __half22float2(hp[0]);
        float2 v1 = __half22float2(hp[1]);
        float2 v2 = __half22float2(hp[2]);
        float2 v3 = __half22float2(hp[3]);
        a0 = ffma2(wp, *(unsigned long long*)&v0, a0);
        a1 = ffma2(wp, *(unsigned long long*)&v1, a1);
        a2 = ffma2(wp, *(unsigned long long*)&v2, a2);
        a3 = ffma2(wp, *(unsigned long long*)&v3, a3);
    }

    float t[8];
    { float2 f0 = *(float2*)&a0, f1 = *(float2*)&a1, f2 = *(float2*)&a2, f3 = *(float2*)&a3;
      t[0]=f0.x; t[1]=f0.y; t[2]=f1.x; t[3]=f1.y; t[4]=f2.x; t[5]=f2.y; t[6]=f3.x; t[7]=f3.y; }
#pragma unroll
    for (int i = 0; i < 8; ++i) {
        t[i] += __shfl_xor_sync(0xffffffffu, t[i], 8);
        t[i] += __shfl_xor_sync(0xffffffffu, t[i], 16);
    }

    float ck = g_coeffs[k];
    if (!fuse) {
        if (sub == 0) {
            // write tout (fp16 chunk, 16B per lane, 128B per warp)
            __half2 o0 = __floats2half2_rn(t[0], t[1]);
            __half2 o1 = __floats2half2_rn(t[2], t[3]);
            __half2 o2 = __floats2half2_rn(t[4], t[5]);
            __half2 o3 = __floats2half2_rn(t[6], t[7]);
            uint4 ov = make_uint4(*(unsigned*)&o0, *(unsigned*)&o1,
                                  *(unsigned*)&o2, *(unsigned*)&o3);
            ((uint4*)tout)[row * 8 + fl] = ov;
            // update res
            float4 r0, r1;
            if (k == 1) {
                float c0 = g_coeffs[0];
                float4 h0 = __ldg((const float4*)g_h + row * 16 + fl * 2);
                float4 h1 = __ldg((const float4*)g_h + row * 16 + fl * 2 + 1);
                r0 = make_float4(c0*h0.x + ck*t[0], c0*h0.y + ck*t[1],
                                 c0*h0.z + ck*t[2], c0*h0.w + ck*t[3]);
                r1 = make_float4(c0*h1.x + ck*t[4], c0*h1.y + ck*t[5],
                                 c0*h1.z + ck*t[6], c0*h1.w + ck*t[7]);
            } else {
                float4 p0 = ((const float4*)g_res)[row * 16 + fl * 2];
                float4 p1 = ((const float4*)g_res)[row * 16 + fl * 2 + 1];
                r0 = make_float4(p0.x + ck*t[0], p0.y + ck*t[1], p0.z + ck*t[2], p0.w + ck*t[3]);
                r1 = make_float4(p1.x + ck*t[4], p1.y + ck*t[5], p1.z + ck*t[6], p1.w + ck*t[7]);
            }
            ((float4*)g_res)[row * 16 + fl * 2]     = r0;
            ((float4*)g_res)[row * 16 + fl * 2 + 1] = r1;
        }
    } else {
        // fused: v = h + res_prev + ck*t, then LayerNorm
        float4 h0 = __ldg((const float4*)g_h + row * 16 + fl * 2);
        float4 h1 = __ldg((const float4*)g_h + row * 16 + fl * 2 + 1);
        float4 p0 = __ldg((const float4*)g_res + row * 16 + fl * 2);
        float4 p1 = __ldg((const float4*)g_res + row * 16 + fl * 2 + 1);
        float v[8];
        v[0]=h0.x+p0.x+ck*t[0]; v[1]=h0.y+p0.y+ck*t[1];
        v[2]=h0.z+p0.z+ck*t[2]; v[3]=h0.w+p0.w+ck*t[3];
        v[4]=h1.x+p1.x+ck*t[4]; v[5]=h1.y+p1.y+ck*t[5];
        v[6]=h1.z+p1.z+ck*t[6]; v[7]=h1.w+p1.w+ck*t[7];
        float ps = 0.f;
#pragma unroll
        for (int i = 0; i < 8; ++i) ps += v[i];
#pragma unroll
        for (int d = 1; d <= 4; d <<= 1) ps += __shfl_xor_sync(0xffffffffu, ps, d);
        float m = ps * (1.0f / HH);
        float q = 0.f;
#pragma unroll
        for (int i = 0; i < 8; ++i) { v[i] -= m; q += v[i] * v[i]; }
#pragma unroll
        for (int d = 1; d <= 4; d <<= 1) q += __shfl_xor_sync(0xffffffffu, q, d);
        float inv = rsqrtf(q * (1.0f / HH) + 1e-5f);
        float4 s0 = __ldg((const float4*)lnsc + fl * 2);
        float4 s1 = __ldg((const float4*)lnsc + fl * 2 + 1);
        float4 b0 = __ldg((const float4*)lnbi + fl * 2);
        float4 b1 = __ldg((const float4*)lnbi + fl * 2 + 1);
        float o[8];
        o[0]=v[0]*inv*s0.x+b0.x; o[1]=v[1]*inv*s0.y+b0.y;
        o[2]=v[2]*inv*s0.z+b0.z; o[3]=v[3]*inv*s0.w+b0.w;
        o[4]=v[4]*inv*s1.x+b1.x; o[5]=v[5]*inv*s1.y+b1.y;
        o[6]=v[6]*inv*s1.z+b1.z; o[7]=v[7]*inv*s1.w+b1.w;
        if (sub == 0) {
            float4 w0 = make_float4(o[0],o[1],o[2],o[3]);
            float4 w1 = make_float4(o[4],o[5],o[6],o[7]);
            ((float4*)g_h)[row * 16 + fl * 2]     = w0;
            ((float4*)g_h)[row * 16 + fl * 2 + 1] = w1;
            __half2 q0 = __floats2half2_rn(o[0],o[1]);
            __half2 q1 = __floats2half2_rn(o[2],o[3]);
            __half2 q2 = __floats2half2_rn(o[4],o[5]);
            __half2 q3 = __floats2half2_rn(o[6],o[7]);
            ((uint4*)g_hh)[row * 8 + fl] = make_uint4(*(unsigned*)&q0, *(unsigned*)&q1,
                                                      *(unsigned*)&q2, *(unsigned*)&q3);
            if (outh) {
                ((float4*)outh)[row * 16 + fl * 2]     = w0;
                ((float4*)outh)[row * 16 + fl * 2 + 1] = w1;
            }
        }
    }
}

// ---------------- edge predictor: A = h@W1a^T, B = h@W1b^T (fp16) ----------------
__global__ void abgemm_kernel(const float* __restrict__ epW1) {
    __shared__ float WtA[64 * 64];
    __shared__ float WtB[64 * 64];
    __shared__ float hs[4 * 64];
    int tid = threadIdx.x;
    for (int idx = tid; idx < 4096; idx += 256) {
        int f = idx >> 6, i = idx & 63;
        WtA[i * 64 + f] = epW1[f * 128 + i];
        WtB[i * 64 + f] = epW1[f * 128 + 64 + i];
    }
    int n0 = blockIdx.x * 4;
    hs[tid] = g_h[n0 * 64 + tid];
    __syncthreads();
    int ln = tid >> 6, f = tid & 63;
    float a = 0.f, b = 0.f;
#pragma unroll
    for (int i = 0; i < 64; ++i) {
        float hv = hs[ln * 64 + i];
        a += hv * WtA[i * 64 + f];
        b += hv * WtB[i * 64 + f];
    }
    g_Ah[(n0 + ln) * 64 + f] = __float2half(a);
    g_Bh[(n0 + ln) * 64 + f] = __float2half(b);
}

// ---------------- edge kernel v2: coop load -> smem transpose -> per-thread MLP ----
__global__ void __launch_bounds__(128)
edge_kernel(const int* __restrict__ ei,
            const float* __restrict__ epb1,
            const float* __restrict__ epW2, const float* __restrict__ epb2,
            const float* __restrict__ epW3, const float* __restrict__ epb3,
            float* __restrict__ out) {
    __shared__ __half2 e1s[32 * 129];   // [feature-pair][edge], stride 129 (conflict-free)
    __shared__ float W2s[32 * 64];
    __shared__ float b2s[32];
    __shared__ float W3s[32];
    __shared__ float b3s;
    int tid = threadIdx.x;
    int w = tid >> 5, lane = tid & 31, sub = lane >> 3, fl = lane & 7;
    for (int idx = tid; idx < 2048; idx += 128) W2s[idx] = epW2[idx];
    if (tid < 32) { b2s[tid] = epb2[tid]; W3s[tid] = epW3[tid]; }
    if (tid == 0) b3s = epb3[0];

    // phase A: each warp fills e1 for its 32 edges (4 edges/step, 8 lanes/edge)
    int base = blockIdx.x * 128 + w * 32;
    int r_own = ei[base + lane];
    int c_own = ei[EE + base + lane];
    float4 bb0 = __ldg((const float4*)epb1 + fl * 2);
    float4 bb1 = __ldg((const float4*)epb1 + fl * 2 + 1);
#pragma unroll
    for (int step = 0; step < 8; ++step) {
        int idx = step * 4 + sub;
        int rj = __shfl_sync(0xffffffffu, r_own, idx);
        int cj = __shfl_sync(0xffffffffu, c_own, idx);
        uint4 a4 = __ldg((const uint4*)g_Ah + rj * 8 + fl);
        uint4 b4 = __ldg((const uint4*)g_Bh + cj * 8 + fl);
        const __half2* ap = (const __half2*)&a4;
        const __half2* bp = (const __half2*)&b4;
        int e_local = w * 32 + idx;
        float2 bias[4] = { make_float2(bb0.x, bb0.y), make_float2(bb0.z, bb0.w),
                           make_float2(bb1.x, bb1.y), make_float2(bb1.z, bb1.w) };
#pragma unroll
        for (int kk = 0; kk < 4; ++kk) {
            float2 av = __half22float2(ap[kk]);
            float2 bv = __half22float2(bp[kk]);
            float vx = fmaxf(av.x + bv.x + bias[kk].x, 0.f);
            float vy = fmaxf(av.y + bv.y + bias[kk].y, 0.f);
            e1s[(fl * 4 + kk) * 129 + e_local] = __floats2half2_rn(vx, vy);
        }
    }
    __syncthreads();

    // phase B: thread per edge
    float2 e1f[32];
#pragma unroll
    for (int f2 = 0; f2 < 32; ++f2)
        e1f[f2] = __half22float2(e1s[f2 * 129 + tid]);
    const unsigned long long* e1p = (const unsigned long long*)e1f;
    float acc = b3s;
#pragma unroll
    for (int o = 0; o < 32; ++o) {
        const unsigned long long* wv = (const unsigned long long*)(W2s + o * 64);
        unsigned long long a2 = pack2(b2s[o], 0.f);
#pragma unroll
        for (int i = 0; i < 32; ++i) a2 = ffma2(wv[i], e1p[i], a2);
        float2 sv = *(const float2*)&a2;
        acc += W3s[o] * fmaxf(sv.x + sv.y, 0.f);
    }
    out[blockIdx.x * 128 + tid] = 1.0f / (1.0f + expf(-acc));
}

// ---------------- launch ----------------
extern "C" void kernel_launch(void* const* d_in, const int* in_sizes, int n_in,
                              void* d_out, int out_size) {
    const float* x    = (const float*)d_in[0];
    const int*   ei   = (const int*)d_in[1];
    const float* ew   = (const float*)d_in[2];
    const float* W_in = (const float*)d_in[3];
    const float* b_in = (const float*)d_in[4];
    const float* cW1  = (const float*)d_in[5];
    const float* cb1  = (const float*)d_in[6];
    const float* cW2  = (const float*)d_in[7];
    const float* cb2  = (const float*)d_in[8];
    const float* lns  = (const float*)d_in[9];
    const float* lnb  = (const float*)d_in[10];
    const float* epW1 = (const float*)d_in[11];
    const float* epb1 = (const float*)d_in[12];
    const float* epW2 = (const float*)d_in[13];
    const float* epb2 = (const float*)d_in[14];
    const float* epW3 = (const float*)d_in[15];
    const float* epb3 = (const float*)d_in[16];
    float* out = (float*)d_out;

    const int NB = (NN + 255) / 256;
    const int EB = (EE + 255) / 256;
    const int WB = (NN * 32 + 255) / 256;   // warp-per-node grids

    zero_build_kernel<<<NB, 256>>>();
    deghist_kernel<<<EB, 256>>>(ei, ew);
    dis_kernel<<<NB, 256>>>();
    scan_partial_kernel<<<NBLK, SCAN_BLK>>>();
    scan_spine_kernel<<<1, SCAN_BLK>>>();
    scan_write_kernel<<<NBLK, SCAN_BLK>>>();
    scatter_kernel<<<EB, 256>>>(ei, ew);

    inproj_kernel<<<(NN * HH + 255) / 256, 256>>>(x, W_in, b_in);

    for (int l = 0; l < LL; ++l) {
        zero_stats_kernel<<<1, 128>>>();
        stats_kernel<<<1024, 256>>>();
        coeff_kernel<<<1, 128>>>(cW1 + l * 32 * CI, cb1 + l * 32,
                                 cW2 + l * (PP + 1) * 32, cb2 + l * (PP + 1));
        for (int k = 1; k < PP; ++k)
            spmm_kernel<<<WB, 256>>>(k, 0, (const float*)nullptr, (const float*)nullptr,
                                     (float*)nullptr);
        spmm_kernel<<<WB, 256>>>(PP, 1, lns + l * HH, lnb + l * HH,
                                 (l == LL - 1) ? (out + EE) : (float*)nullptr);
    }

    abgemm_kernel<<<NN / 4, 256>>>(epW1);
    edge_kernel<<<(EE + 127) / 128, 128>>>(ei, epb1, epW2, epb2, epW3, epb3, out);
}

// round 4
// speedup vs baseline: 1.5300x; 1.2008x over previous
#include <cuda_runtime.h>
#include <cuda_fp16.h>
#include <mma.h>
#include <math.h>

using namespace nvcuda;

#define NN 50000
#define EE 1600000
#define HH 64
#define FIN 8
#define PP 5
#define LL 3
#define CI 68   // H + 4
#define SCAN_BLK 256
#define NBLK ((NN + SCAN_BLK - 1) / SCAN_BLK)   // 196
#define SG 240  // stats grid

// ---------------- scratch (device globals; no allocation) ----------------
__device__ __align__(128) float g_deg[NN];
__device__ __align__(128) float g_dis[NN];
__device__ __align__(128) int   g_cnt[NN];
__device__ __align__(128) int   g_fill[NN];
__device__ __align__(128) int   g_rowptr[NN + 1];
__device__ __align__(128) int   g_part[SCAN_BLK];
__device__ __align__(128) int2  g_cw[EE + 8];     // packed (col, w-bits), padded
__device__ __align__(128) float g_h[NN * HH];     // fp32 master h
__device__ __align__(128) __half g_hh[NN * HH];   // fp16 mirror of h
__device__ __align__(128) __half g_t0h[NN * HH];  // fp16 tx ping
__device__ __align__(128) __half g_t1h[NN * HH];  // fp16 tx pong
__device__ __align__(128) float g_res[NN * HH];
__device__ __align__(128) __half g_Ah[NN * HH];   // edge-pred A (fp16)
__device__ __align__(128) __half g_Bh[NN * HH];   // edge-pred B (fp16)
__device__ __align__(128) float g_pcol[SG][HH];   // stats partials
__device__ __align__(128) float g_psq[SG];
__device__ float g_coeffs[PP + 1];

// packed dual-fp32 FMA (sm_103a)
__device__ __forceinline__ unsigned long long ffma2(unsigned long long a,
                                                    unsigned long long b,
                                                    unsigned long long c) {
    unsigned long long d;
    asm("fma.rn.f32x2 %0, %1, %2, %3;" : "=l"(d) : "l"(a), "l"(b), "l"(c));
    return d;
}
__device__ __forceinline__ unsigned long long pack2(float x, float y) {
    float2 t = make_float2(x, y);
    return *(unsigned long long*)&t;
}

// ---------------- graph build ----------------
__global__ void zero_build_kernel() {
    int i = blockIdx.x * blockDim.x + threadIdx.x;
    if (i < NN) { g_deg[i] = 0.f; g_cnt[i] = 0; g_fill[i] = 0; }
}

__global__ void deghist_kernel(const int* __restrict__ ei, const float* __restrict__ ew) {
    int e = blockIdx.x * blockDim.x + threadIdx.x;
    if (e >= EE) return;
    atomicAdd(&g_deg[ei[EE + e]], ew[e]);
    atomicAdd(&g_cnt[ei[e]], 1);
}

// fused: dis + per-block count reduction
__global__ void scan_partial_kernel() {
    __shared__ int red[SCAN_BLK];
    int tid = threadIdx.x;
    int i = blockIdx.x * SCAN_BLK + tid;
    if (i < NN) {
        float v = rsqrtf(g_deg[i]);
        g_dis[i] = fminf(v, 1e6f);
    }
    red[tid] = (i < NN) ? g_cnt[i] : 0;
    __syncthreads();
    for (int o = SCAN_BLK / 2; o > 0; o >>= 1) {
        if (tid < o) red[tid] += red[tid + o];
        __syncthreads();
    }
    if (tid == 0) g_part[blockIdx.x] = red[0];
}

__global__ void scan_spine_kernel() {
    __shared__ int s[SCAN_BLK];
    int tid = threadIdx.x;
    s[tid] = (tid < NBLK) ? g_part[tid] : 0;
    __syncthreads();
    for (int o = 1; o < SCAN_BLK; o <<= 1) {
        int t = (tid >= o) ? s[tid - o] : 0;
        __syncthreads();
        s[tid] += t;
        __syncthreads();
    }
    g_part[tid] = (tid == 0) ? 0 : s[tid - 1];
    if (tid == SCAN_BLK - 1) g_rowptr[NN] = s[tid];
}

__global__ void scan_write_kernel() {
    __shared__ int s[SCAN_BLK];
    int tid = threadIdx.x;
    int i = blockIdx.x * SCAN_BLK + tid;
    int v = (i < NN) ? g_cnt[i] : 0;
    s[tid] = v;
    __syncthreads();
    for (int o = 1; o < SCAN_BLK; o <<= 1) {
        int t = (tid >= o) ? s[tid - o] : 0;
        __syncthreads();
        s[tid] += t;
        __syncthreads();
    }
    if (i < NN) g_rowptr[i] = g_part[blockIdx.x] + s[tid] - v;
}

__global__ void scatter_kernel(const int* __restrict__ ei, const float* __restrict__ ew) {
    int e = blockIdx.x * blockDim.x + threadIdx.x;
    if (e >= EE) return;
    int r = ei[e], c = ei[EE + e];
    int pos = g_rowptr[r] + atomicAdd(&g_fill[r], 1);
    float w = g_dis[r] * ew[e] * g_dis[c];
    g_cw[pos] = make_int2(c, __float_as_int(w));
}

// ---------------- input projection ----------------
__global__ void inproj_kernel(const float* __restrict__ x,
                              const float* __restrict__ W,
                              const float* __restrict__ b) {
    int g = blockIdx.x * blockDim.x + threadIdx.x;
    if (g >= NN * HH) return;
    int n = g >> 6, f = g & 63;
    float s = b[f];
#pragma unroll
    for (int i = 0; i < FIN; ++i) s += x[n * FIN + i] * W[f * FIN + i];
    g_h[g] = s;
    g_hh[g] = __float2half(s);
}

// ---------------- per-layer stats (no atomics) + coeff MLP ----------------
__global__ void stats_kernel() {
    __shared__ float red[256];
    int tid = threadIdx.x;
    int colf = tid & 63;
    float ls = 0.f, lss = 0.f;
    for (int n = blockIdx.x * 4 + (tid >> 6); n < NN; n += SG * 4) {
        float v = g_h[n * HH + colf];
        ls += v; lss += v * v;
    }
    red[tid] = ls;
    __syncthreads();
    if (tid < 64)
        g_pcol[blockIdx.x][tid] = red[tid] + red[tid + 64] + red[tid + 128] + red[tid + 192];
    __syncthreads();
    red[tid] = lss;
    __syncthreads();
    for (int o = 128; o > 0; o >>= 1) {
        if (tid < o) red[tid] += red[tid + o];
        __syncthreads();
    }
    if (tid == 0) g_psq[blockIdx.x] = red[0];
}

__global__ void coeff_kernel(const float* __restrict__ cW1, const float* __restrict__ cb1,
                             const float* __restrict__ cW2, const float* __restrict__ cb2) {
    __shared__ float colsum[HH];
    __shared__ float ci[CI];
    __shared__ float hid[32];
    __shared__ float logit[PP + 1];
    __shared__ float sq_s;
    int t = threadIdx.x;
    if (t < HH) {
        float s = 0.f;
        for (int b = 0; b < SG; ++b) s += g_pcol[b][t];
        colsum[t] = s;
        ci[t] = s / (float)NN;
    } else if (t >= 64 && t < 96) {
        int l = t - 64;
        float s = 0.f;
        for (int b = l; b < SG; b += 32) s += g_psq[b];
#pragma unroll
        for (int d = 16; d; d >>= 1) s += __shfl_xor_sync(0xffffffffu, s, d);
        if (l == 0) sq_s = s;
    }
    __syncthreads();
    if (t == 0) {
        float tot = 0.f;
        for (int i = 0; i < HH; ++i) tot += colsum[i];
        const float M = (float)NN * (float)HH;
        float mean = tot / M;
        float var  = (sq_s - tot * tot / M) / (M - 1.0f);
        ci[64] = mean;
        ci[65] = sqrtf(fmaxf(var, 0.f));
        ci[66] = (float)NN;
        ci[67] = (float)EE;
    }
    __syncthreads();
    if (t < 32) {
        float s = cb1[t];
        for (int i = 0; i < CI; ++i) s += cW1[t * CI + i] * ci[i];
        hid[t] = fmaxf(s, 0.f);
    }
    __syncthreads();
    if (t < PP + 1) {
        float s = cb2[t];
        for (int i = 0; i < 32; ++i) s += cW2[t * 32 + i] * hid[i];
        logit[t] = s;
    }
    __syncthreads();
    if (t == 0) {
        float mx = logit[0];
        for (int i = 1; i <= PP; ++i) mx = fmaxf(mx, logit[i]);
        float den = 0.f, ex[PP + 1];
        for (int i = 0; i <= PP; ++i) { ex[i] = expf(logit[i] - mx); den += ex[i]; }
        for (int i = 0; i <= PP; ++i) g_coeffs[i] = ex[i] / den;
    }
}

// ---------------- SpMM v4: warp per row, 8 neighbors/iter (software pipelined) ----------
template <int FUSE>
__global__ void spmm_kernel(int k,
                            const float* __restrict__ lnsc,
                            const float* __restrict__ lnbi,
                            float* outh) {
    int row = (blockIdx.x * blockDim.x + threadIdx.x) >> 5;
    if (row >= NN) return;
    int lane = threadIdx.x & 31;
    int sub = lane >> 3, fl = lane & 7;

    const __half* tin = (k == 1) ? g_hh : ((k & 1) ? g_t1h : g_t0h);
    __half* tout = (k & 1) ? g_t0h : g_t1h;

    int s = g_rowptr[row], e = g_rowptr[row + 1];
    unsigned long long a0 = 0ull, a1 = 0ull, a2 = 0ull, a3 = 0ull;

    for (int jb = s; jb < e; jb += 8) {
        int jA = jb + sub, jB = jb + 4 + sub;
        int2 cwA = __ldg(&g_cw[jA]);
        int2 cwB = __ldg(&g_cw[jB]);
        int ccA = (jA < e) ? cwA.x : 0;
        float wAv = (jA < e) ? __int_as_float(cwA.y) : 0.f;
        int ccB = (jB < e) ? cwB.x : 0;
        float wBv = (jB < e) ? __int_as_float(cwB.y) : 0.f;
        uint4 dA = __ldg((const uint4*)tin + ccA * 8 + fl);
        uint4 dB = __ldg((const uint4*)tin + ccB * 8 + fl);
        unsigned long long wpA = pack2(wAv, wAv);
        unsigned long long wpB = pack2(wBv, wBv);
        const __half2* hpA = (const __half2*)&dA;
        const __half2* hpB = (const __half2*)&dB;
        float2 vA0 = __half22float2(hpA[0]), vA1 = __half22float2(hpA[1]);
        float2 vA2 = __half22float2(hpA[2]), vA3 = __half22float2(hpA[3]);
        float2 vB0 = __half22float2(hpB[0]), vB1 = __half22float2(hpB[1]);
        float2 vB2 = __half22float2(hpB[2]), vB3 = __half22float2(hpB[3]);
        a0 = ffma2(wpA, *(unsigned long long*)&vA0, a0);
        a1 = ffma2(wpA, *(unsigned long long*)&vA1, a1);
        a2 = ffma2(wpA, *(unsigned long long*)&vA2, a2);
        a3 = ffma2(wpA, *(unsigned long long*)&vA3, a3);
        a0 = ffma2(wpB, *(unsigned long long*)&vB0, a0);
        a1 = ffma2(wpB, *(unsigned long long*)&vB1, a1);
        a2 = ffma2(wpB, *(unsigned long long*)&vB2, a2);
        a3 = ffma2(wpB, *(unsigned long long*)&vB3, a3);
    }

    float t[8];
    { float2 f0 = *(float2*)&a0, f1 = *(float2*)&a1, f2 = *(float2*)&a2, f3 = *(float2*)&a3;
      t[0]=f0.x; t[1]=f0.y; t[2]=f1.x; t[3]=f1.y; t[4]=f2.x; t[5]=f2.y; t[6]=f3.x; t[7]=f3.y; }
#pragma unroll
    for (int i = 0; i < 8; ++i) {
        t[i] += __shfl_xor_sync(0xffffffffu, t[i], 8);
        t[i] += __shfl_xor_sync(0xffffffffu, t[i], 16);
    }

    float ck = g_coeffs[k];
    if (!FUSE) {
        if (sub == 0) {
            __half2 o0 = __floats2half2_rn(t[0], t[1]);
            __half2 o1 = __floats2half2_rn(t[2], t[3]);
            __half2 o2 = __floats2half2_rn(t[4], t[5]);
            __half2 o3 = __floats2half2_rn(t[6], t[7]);
            ((uint4*)tout)[row * 8 + fl] = make_uint4(*(unsigned*)&o0, *(unsigned*)&o1,
                                                      *(unsigned*)&o2, *(unsigned*)&o3);
            float4 r0, r1;
            if (k == 1) {
                float c0 = g_coeffs[0];
                float4 h0 = __ldg((const float4*)g_h + row * 16 + fl * 2);
                float4 h1 = __ldg((const float4*)g_h + row * 16 + fl * 2 + 1);
                r0 = make_float4(c0*h0.x + ck*t[0], c0*h0.y + ck*t[1],
                                 c0*h0.z + ck*t[2], c0*h0.w + ck*t[3]);
                r1 = make_float4(c0*h1.x + ck*t[4], c0*h1.y + ck*t[5],
                                 c0*h1.z + ck*t[6], c0*h1.w + ck*t[7]);
            } else {
                float4 p0 = ((const float4*)g_res)[row * 16 + fl * 2];
                float4 p1 = ((const float4*)g_res)[row * 16 + fl * 2 + 1];
                r0 = make_float4(p0.x + ck*t[0], p0.y + ck*t[1], p0.z + ck*t[2], p0.w + ck*t[3]);
                r1 = make_float4(p1.x + ck*t[4], p1.y + ck*t[5], p1.z + ck*t[6], p1.w + ck*t[7]);
            }
            ((float4*)g_res)[row * 16 + fl * 2]     = r0;
            ((float4*)g_res)[row * 16 + fl * 2 + 1] = r1;
        }
    } else {
        float4 h0 = __ldg((const float4*)g_h + row * 16 + fl * 2);
        float4 h1 = __ldg((const float4*)g_h + row * 16 + fl * 2 + 1);
        float4 p0 = __ldg((const float4*)g_res + row * 16 + fl * 2);
        float4 p1 = __ldg((const float4*)g_res + row * 16 + fl * 2 + 1);
        float v[8];
        v[0]=h0.x+p0.x+ck*t[0]; v[1]=h0.y+p0.y+ck*t[1];
        v[2]=h0.z+p0.z+ck*t[2]; v[3]=h0.w+p0.w+ck*t[3];
        v[4]=h1.x+p1.x+ck*t[4]; v[5]=h1.y+p1.y+ck*t[5];
        v[6]=h1.z+p1.z+ck*t[6]; v[7]=h1.w+p1.w+ck*t[7];
        float ps = 0.f;
#pragma unroll
        for (int i = 0; i < 8; ++i) ps += v[i];
#pragma unroll
        for (int d = 1; d <= 4; d <<= 1) ps += __shfl_xor_sync(0xffffffffu, ps, d);
        float m = ps * (1.0f / HH);
        float q = 0.f;
#pragma unroll
        for (int i = 0; i < 8; ++i) { v[i] -= m; q += v[i] * v[i]; }
#pragma unroll
        for (int d = 1; d <= 4; d <<= 1) q += __shfl_xor_sync(0xffffffffu, q, d);
        float inv = rsqrtf(q * (1.0f / HH) + 1e-5f);
        float4 s0 = __ldg((const float4*)lnsc + fl * 2);
        float4 s1 = __ldg((const float4*)lnsc + fl * 2 + 1);
        float4 b0 = __ldg((const float4*)lnbi + fl * 2);
        float4 b1 = __ldg((const float4*)lnbi + fl * 2 + 1);
        float o[8];
        o[0]=v[0]*inv*s0.x+b0.x; o[1]=v[1]*inv*s0.y+b0.y;
        o[2]=v[2]*inv*s0.z+b0.z; o[3]=v[3]*inv*s0.w+b0.w;
        o[4]=v[4]*inv*s1.x+b1.x; o[5]=v[5]*inv*s1.y+b1.y;
        o[6]=v[6]*inv*s1.z+b1.z; o[7]=v[7]*inv*s1.w+b1.w;
        if (sub == 0) {
            float4 w0 = make_float4(o[0],o[1],o[2],o[3]);
            float4 w1 = make_float4(o[4],o[5],o[6],o[7]);
            ((float4*)g_h)[row * 16 + fl * 2]     = w0;
            ((float4*)g_h)[row * 16 + fl * 2 + 1] = w1;
            __half2 q0 = __floats2half2_rn(o[0],o[1]);
            __half2 q1 = __floats2half2_rn(o[2],o[3]);
            __half2 q2 = __floats2half2_rn(o[4],o[5]);
            __half2 q3 = __floats2half2_rn(o[6],o[7]);
            ((uint4*)g_hh)[row * 8 + fl] = make_uint4(*(unsigned*)&q0, *(unsigned*)&q1,
                                                      *(unsigned*)&q2, *(unsigned*)&q3);
            if (outh) {
                ((float4*)outh)[row * 16 + fl * 2]     = w0;
                ((float4*)outh)[row * 16 + fl * 2 + 1] = w1;
            }
        }
    }
}

// ---------------- edge predictor: A = h@W1a^T, B = h@W1b^T (fp16) ----------------
__global__ void abgemm_kernel(const float* __restrict__ epW1) {
    __shared__ float WtA[64 * 64];
    __shared__ float WtB[64 * 64];
    __shared__ float hs[4 * 64];
    int tid = threadIdx.x;
    for (int idx = tid; idx < 4096; idx += 256) {
        int f = idx >> 6, i = idx & 63;
        WtA[i * 64 + f] = epW1[f * 128 + i];
        WtB[i * 64 + f] = epW1[f * 128 + 64 + i];
    }
    int n0 = blockIdx.x * 4;
    hs[tid] = g_h[n0 * 64 + tid];
    __syncthreads();
    int ln = tid >> 6, f = tid & 63;
    float a = 0.f, b = 0.f;
#pragma unroll
    for (int i = 0; i < 64; ++i) {
        float hv = hs[ln * 64 + i];
        a += hv * WtA[i * 64 + f];
        b += hv * WtB[i * 64 + f];
    }
    g_Ah[(n0 + ln) * 64 + f] = __float2half(a);
    g_Bh[(n0 + ln) * 64 + f] = __float2half(b);
}

// ---------------- edge kernel v3: coop gather -> wmma second layer ----------------
#define E1LD 72   // padded half stride (144B, mult of 16B)
#define E2LD 36   // padded float stride (144B)
__global__ void __launch_bounds__(128)
edge_kernel(const int* __restrict__ ei,
            const float* __restrict__ epb1,
            const float* __restrict__ epW2, const float* __restrict__ epb2,
            const float* __restrict__ epW3, const float* __restrict__ epb3,
            float* __restrict__ out) {
    __shared__ __half e1s[128 * E1LD];  // [edge][feat]
    __shared__ __half W2h[32 * 64];     // [out][feat] == col-major B (feat x out)
    __shared__ float  e2s[128 * E2LD];  // [edge][out]
    __shared__ float  b2s[32], W3s[32];
    __shared__ float  b3s;
    int tid = threadIdx.x;
    int w = tid >> 5, lane = tid & 31, sub = lane >> 3, fl = lane & 7;
    for (int idx = tid; idx < 2048; idx += 128) W2h[idx] = __float2half(epW2[idx]);
    if (tid < 32) { b2s[tid] = epb2[tid]; W3s[tid] = epW3[tid]; }
    if (tid == 0) b3s = epb3[0];
    __syncthreads();

    // phase A: warp computes e1 for its 32 edges (4 edges/step, 8 lanes/edge)
    int base = blockIdx.x * 128 + w * 32;
    int r_own = ei[base + lane];
    int c_own = ei[EE + base + lane];
    float4 bb0 = __ldg((const float4*)epb1 + fl * 2);
    float4 bb1 = __ldg((const float4*)epb1 + fl * 2 + 1);
    float2 bias[4] = { make_float2(bb0.x, bb0.y), make_float2(bb0.z, bb0.w),
                       make_float2(bb1.x, bb1.y), make_float2(bb1.z, bb1.w) };
#pragma unroll
    for (int step = 0; step < 8; ++step) {
        int idx = step * 4 + sub;
        int rj = __shfl_sync(0xffffffffu, r_own, idx);
        int cj = __shfl_sync(0xffffffffu, c_own, idx);
        uint4 a4 = __ldg((const uint4*)g_Ah + rj * 8 + fl);
        uint4 b4 = __ldg((const uint4*)g_Bh + cj * 8 + fl);
        const __half2* ap = (const __half2*)&a4;
        const __half2* bp = (const __half2*)&b4;
        int e_local = w * 32 + idx;
#pragma unroll
        for (int kk = 0; kk < 4; ++kk) {
            float2 av = __half22float2(ap[kk]);
            float2 bv = __half22float2(bp[kk]);
            float vx = fmaxf(av.x + bv.x + bias[kk].x, 0.f);
            float vy = fmaxf(av.y + bv.y + bias[kk].y, 0.f);
            *(__half2*)(e1s + e_local * E1LD + (fl * 4 + kk) * 2) = __floats2half2_rn(vx, vy);
        }
    }
    __syncwarp();

    // phase B: wmma, per warp over its 32 edges
    wmma::fragment<wmma::matrix_b, 16, 16, 16, __half, wmma::col_major> bf[4][2];
#pragma unroll
    for (int kk = 0; kk < 4; ++kk)
#pragma unroll
        for (int n = 0; n < 2; ++n)
            wmma::load_matrix_sync(bf[kk][n], W2h + n * 16 * 64 + kk * 16, 64);
#pragma unroll
    for (int m = 0; m < 2; ++m) {
        wmma::fragment<wmma::accumulator, 16, 16, 16, float> cf[2];
        wmma::fill_fragment(cf[0], 0.f);
        wmma::fill_fragment(cf[1], 0.f);
#pragma unroll
        for (int kk = 0; kk < 4; ++kk) {
            wmma::fragment<wmma::matrix_a, 16, 16, 16, __half, wmma::row_major> af;
            wmma::load_matrix_sync(af, e1s + (w * 32 + m * 16) * E1LD + kk * 16, E1LD);
            wmma::mma_sync(cf[0], af, bf[kk][0], cf[0]);
            wmma::mma_sync(cf[1], af, bf[kk][1], cf[1]);
        }
        wmma::store_matrix_sync(e2s + (w * 32 + m * 16) * E2LD, cf[0], E2LD, wmma::mem_row_major);
        wmma::store_matrix_sync(e2s + (w * 32 + m * 16) * E2LD + 16, cf[1], E2LD, wmma::mem_row_major);
    }
    __syncwarp();

    // readout: thread per edge
    const float* rowp = e2s + tid * E2LD;
    float acc = b3s;
#pragma unroll
    for (int o = 0; o < 32; ++o)
        acc += W3s[o] * fmaxf(rowp[o] + b2s[o], 0.f);
    out[blockIdx.x * 128 + tid] = 1.0f / (1.0f + expf(-acc));
}

// ---------------- launch ----------------
extern "C" void kernel_launch(void* const* d_in, const int* in_sizes, int n_in,
                              void* d_out, int out_size) {
    const float* x    = (const float*)d_in[0];
    const int*   ei   = (const int*)d_in[1];
    const float* ew   = (const float*)d_in[2];
    const float* W_in = (const float*)d_in[3];
    const float* b_in = (const float*)d_in[4];
    const float* cW1  = (const float*)d_in[5];
    const float* cb1  = (const float*)d_in[6];
    const float* cW2  = (const float*)d_in[7];
    const float* cb2  = (const float*)d_in[8];
    const float* lns  = (const float*)d_in[9];
    const float* lnb  = (const float*)d_in[10];
    const float* epW1 = (const float*)d_in[11];
    const float* epb1 = (const float*)d_in[12];
    const float* epW2 = (const float*)d_in[13];
    const float* epb2 = (const float*)d_in[14];
    const float* epW3 = (const float*)d_in[15];
    const float* epb3 = (const float*)d_in[16];
    float* out = (float*)d_out;

    const int NB = (NN + 255) / 256;
    const int EB = (EE + 255) / 256;
    const int WB = (NN * 32 + 255) / 256;

    zero_build_kernel<<<NB, 256>>>();
    deghist_kernel<<<EB, 256>>>(ei, ew);
    scan_partial_kernel<<<NBLK, SCAN_BLK>>>();   // + dis fused
    scan_spine_kernel<<<1, SCAN_BLK>>>();
    scan_write_kernel<<<NBLK, SCAN_BLK>>>();
    scatter_kernel<<<EB, 256>>>(ei, ew);

    inproj_kernel<<<(NN * HH + 255) / 256, 256>>>(x, W_in, b_in);

    for (int l = 0; l < LL; ++l) {
        stats_kernel<<<SG, 256>>>();
        coeff_kernel<<<1, 128>>>(cW1 + l * 32 * CI, cb1 + l * 32,
                                 cW2 + l * (PP + 1) * 32, cb2 + l * (PP + 1));
        for (int k = 1; k < PP; ++k)
            spmm_kernel<0><<<WB, 256>>>(k, (const float*)nullptr, (const float*)nullptr,
                                        (float*)nullptr);
        spmm_kernel<1><<<WB, 256>>>(PP, lns + l * HH, lnb + l * HH,
                                    (l == LL - 1) ? (out + EE) : (float*)nullptr);
    }

    abgemm_kernel<<<NN / 4, 256>>>(epW1);
    edge_kernel<<<(EE + 127) / 128, 128>>>(ei, epb1, epW2, epb2, epW3, epb3, out);
}